// round 11
// baseline (speedup 1.0000x reference)
#include <cuda_runtime.h>
#include <cuda_fp16.h>
#include <cstdint>

#define BATCH 8192
#define NFEAT 32
#define EDIM  64
#define VOCAB 1000
#define NPAIR 496
#define DIN   2544
#define K1P   2560
#define DH1   1024
#define DH2   512
#define DOUT  1000
#define N3P   1024

typedef __half f16;

// ---------------- scratch (device globals; no runtime allocation) ----------
__device__ f16 g_h0[(size_t)BATCH * K1P];
__device__ f16 g_h1[(size_t)BATCH * DH1];
__device__ f16 g_h2[(size_t)BATCH * DH2];
__device__ f16 g_W1[(size_t)DH1 * K1P];
__device__ f16 g_W2[(size_t)DH2 * DH1];
__device__ f16 g_W3[(size_t)N3P * DH2];

// ---------------- helpers ---------------------------------------------------
__device__ __forceinline__ uint32_t smem_u32(const void* p) {
    return (uint32_t)__cvta_generic_to_shared(p);
}
__device__ __forceinline__ void cp_async16(uint32_t dst, const void* src) {
    asm volatile("cp.async.cg.shared.global [%0], [%1], 16;\n" :: "r"(dst), "l"(src));
}
__device__ __forceinline__ void ldsm4(uint32_t addr, uint32_t& r0, uint32_t& r1,
                                      uint32_t& r2, uint32_t& r3) {
    asm volatile("ldmatrix.sync.aligned.m8n8.x4.shared.b16 {%0,%1,%2,%3}, [%4];\n"
                 : "=r"(r0), "=r"(r1), "=r"(r2), "=r"(r3) : "r"(addr));
}
__device__ __forceinline__ void mma_fp16(float c[4], const uint32_t a[4],
                                         uint32_t b0, uint32_t b1) {
    asm volatile("mma.sync.aligned.m16n8k16.row.col.f32.f16.f16.f32 "
                 "{%0,%1,%2,%3},{%4,%5,%6,%7},{%8,%9},{%0,%1,%2,%3};\n"
                 : "+f"(c[0]), "+f"(c[1]), "+f"(c[2]), "+f"(c[3])
                 : "r"(a[0]), "r"(a[1]), "r"(a[2]), "r"(a[3]), "r"(b0), "r"(b1));
}

// ---------------------------------------------------------------------------
// Fused prep kernel: weight converts + feature build (unchanged from R10)
// ---------------------------------------------------------------------------
#define CONV1_BLKS 2560
#define CONV2_BLKS 512
#define CONV3_BLKS 512
#define CONV_BLKS  (CONV1_BLKS + CONV2_BLKS + CONV3_BLKS)   // 3584
#define FEAT_BLKS  (BATCH / 8)                               // 1024
#define PREP_BLKS  (CONV_BLKS + FEAT_BLKS)                   // 4608

#define FB_E_STRIDE 72
#define FB_WARP_BYTES (32 * FB_E_STRIDE * 2 + 32 * 36 * 2)   // 6912
#define FB_PAIRS_BYTES 2048
#define PREP_SMEM (FB_PAIRS_BYTES + 8 * FB_WARP_BYTES)       // 57344

__device__ __forceinline__ void convert_body(char* sm,
                                             const float* __restrict__ W,
                                             f16* __restrict__ dst,
                                             int K, int N, int Kpad, int Npad,
                                             int cid, int nbx) {
    float (*t)[33] = (float(*)[33])sm;
    const int tx = threadIdx.x & 31;
    const int ty = threadIdx.x >> 5;
    const int n0 = (cid % nbx) * 32;
    const int k0 = (cid / nbx) * 32;
    for (int r = ty; r < 32; r += 8) {
        int k = k0 + r, n = n0 + tx;
        t[r][tx] = (k < K && n < N) ? W[(size_t)k * N + n] : 0.f;
    }
    __syncthreads();
    for (int r = ty; r < 32; r += 8) {
        int n = n0 + r, k = k0 + tx;
        if (n < Npad && k < Kpad)
            dst[(size_t)n * Kpad + k] = __float2half_rn(t[tx][r]);
    }
}

__global__ __launch_bounds__(256)
void prep_kernel(const int* __restrict__ x,
                 const float* __restrict__ emb,
                 const float* __restrict__ W1,
                 const float* __restrict__ W2,
                 const float* __restrict__ W3,
                 f16* __restrict__ w1, f16* __restrict__ w2, f16* __restrict__ w3,
                 f16* __restrict__ h0) {
    extern __shared__ __align__(16) char sm[];
    const int bid = blockIdx.x;

    if (bid < CONV1_BLKS) {
        convert_body(sm, W1, w1, DIN, DH1, K1P, DH1, bid, 32);
        return;
    }
    if (bid < CONV1_BLKS + CONV2_BLKS) {
        convert_body(sm, W2, w2, DH1, DH2, DH1, DH2, bid - CONV1_BLKS, 16);
        return;
    }
    if (bid < CONV_BLKS) {
        convert_body(sm, W3, w3, DH2, DOUT, DH2, N3P, bid - CONV1_BLKS - CONV2_BLKS, 32);
        return;
    }

    // ---------------- features ----------------
    const int fb   = bid - CONV_BLKS;
    const int tid  = threadIdx.x;
    const int wid  = tid >> 5;
    const int lane = tid & 31;
    const int b    = fb * 8 + wid;

    int* pairs_s = (int*)sm;
    f16* e_s    = (f16*)(sm + FB_PAIRS_BYTES + wid * FB_WARP_BYTES);
    f16* gram_s = e_s + 32 * FB_E_STRIDE;

    for (int p = tid; p < NPAIR; p += 256) {
        int i = 0, s = 0;
        while (p >= s + (NFEAT - 1 - i)) { s += NFEAT - 1 - i; i++; }
        pairs_s[p] = (i << 8) | (i + 1 + (p - s));
    }
    __syncthreads();

    const size_t base = (size_t)b * K1P;

    {
        const int f = lane;
        const int myidx = x[b * NFEAT + f];
        const float* src = emb + ((size_t)f * VOCAB + myidx) * EDIM;
        uint4 ob[8];
        #pragma unroll
        for (int q = 0; q < 8; q++) {
            const float4 v0 = *(const float4*)(src + q * 8);
            const float4 v1 = *(const float4*)(src + q * 8 + 4);
            __half2 p0 = __floats2half2_rn(v0.x, v0.y);
            __half2 p1 = __floats2half2_rn(v0.z, v0.w);
            __half2 p2 = __floats2half2_rn(v1.x, v1.y);
            __half2 p3 = __floats2half2_rn(v1.z, v1.w);
            ob[q] = make_uint4(*(uint32_t*)&p0, *(uint32_t*)&p1,
                               *(uint32_t*)&p2, *(uint32_t*)&p3);
            *(uint4*)(e_s + f * FB_E_STRIDE + q * 8) = ob[q];
        }
        #pragma unroll
        for (int q = 0; q < 8; q++)
            *(uint4*)(h0 + base + f * EDIM + q * 8) = ob[q];
    }
    __syncwarp();

    {
        const int la_row = lane & 15;
        const int la_col = (lane >> 4) << 3;
        const int lb_row = (lane & 7) + ((lane >> 4) << 3);
        const int lb_col = ((lane >> 3) & 1) << 3;

        float acc[2][4][4];
        #pragma unroll
        for (int mi = 0; mi < 2; mi++)
            #pragma unroll
            for (int nb = 0; nb < 4; nb++)
                #pragma unroll
                for (int q = 0; q < 4; q++) acc[mi][nb][q] = 0.f;

        #pragma unroll
        for (int ks = 0; ks < EDIM; ks += 16) {
            uint32_t ar[2][4], br[2][4];
            #pragma unroll
            for (int mi = 0; mi < 2; mi++) {
                const uint32_t off = (uint32_t)(((mi * 16 + la_row) * FB_E_STRIDE
                                                 + ks + la_col) * 2);
                ldsm4(smem_u32(e_s) + off, ar[mi][0], ar[mi][1], ar[mi][2], ar[mi][3]);
            }
            #pragma unroll
            for (int np = 0; np < 2; np++) {
                const uint32_t off = (uint32_t)(((np * 16 + lb_row) * FB_E_STRIDE
                                                 + ks + lb_col) * 2);
                ldsm4(smem_u32(e_s) + off, br[np][0], br[np][1], br[np][2], br[np][3]);
            }
            #pragma unroll
            for (int mi = 0; mi < 2; mi++)
                #pragma unroll
                for (int nb = 0; nb < 4; nb++)
                    mma_fp16(acc[mi][nb], ar[mi],
                             br[nb >> 1][(nb & 1) * 2],
                             br[nb >> 1][(nb & 1) * 2 + 1]);
        }

        #pragma unroll
        for (int mi = 0; mi < 2; mi++) {
            #pragma unroll
            for (int nb = 0; nb < 4; nb++) {
                const int r0 = mi * 16 + (lane >> 2);
                const int c0 = nb * 8 + (lane & 3) * 2;
                *(__half2*)(gram_s + r0 * 36 + c0) =
                    __floats2half2_rn(acc[mi][nb][0], acc[mi][nb][1]);
                *(__half2*)(gram_s + (r0 + 8) * 36 + c0) =
                    __floats2half2_rn(acc[mi][nb][2], acc[mi][nb][3]);
            }
        }
    }
    __syncwarp();

    for (int p = lane; p < NPAIR; p += 32) {
        const int pr = pairs_s[p];
        h0[base + NFEAT * EDIM + p] = gram_s[(pr >> 8) * 36 + (pr & 255)];
    }
    if (lane < K1P - DIN) h0[base + DIN + lane] = __float2half(0.f);
}

// ---------------------------------------------------------------------------
// Persistent fp16 tensor-core GEMM: C[M,N] = act( A @ B^T + bias )
// BM=256, BN=64, BK=64; 256 threads, warps 4(m) x 2(n), warp tile 64x32.
// 2-stage cp.async ring; 2 CTAs/SM; CTAs loop over tiles (col-fastest).
// ---------------------------------------------------------------------------
#define BM 256
#define BN 64
#define BKC 64
#define SPAD 72                           // halfs per row = 144B (16B-aligned)
#define A_BYTES (BM * SPAD * 2)           // 36864
#define B_BYTES (BN * SPAD * 2)           // 9216
#define STAGE_BYTES (A_BYTES + B_BYTES)   // 46080
#define SMEM_TOTAL (2 * STAGE_BYTES)      // 92160
#define GEMM_GRID 296                     // 2 * 148 SMs

template<int ACT>
__global__ __launch_bounds__(256, 2)
void mma_gemm_kernel(const f16* __restrict__ A, const f16* __restrict__ B,
                     const float* __restrict__ bias,
                     f16* __restrict__ Ch, float* __restrict__ Cf,
                     int Kp, int ldc, int nchunk, int ntiles, int ncolt) {
    extern __shared__ __align__(16) char smem[];

    const int tid  = threadIdx.x;
    const int lane = tid & 31;
    const int wid  = tid >> 5;
    const int wm   = (wid >> 1) * 64;
    const int wn   = (wid & 1) * 32;

    const int la_row = lane & 15;
    const int la_col = (lane >> 4) << 3;
    const int lb_row = (lane & 7) + ((lane >> 4) << 3);
    const int lb_col = ((lane >> 3) & 1) << 3;

    for (int t = blockIdx.x; t < ntiles; t += gridDim.x) {
        const int row0 = (t / ncolt) * BM;
        const int col0 = (t % ncolt) * BN;

        float acc[4][4][4];
        #pragma unroll
        for (int mi = 0; mi < 4; mi++)
            #pragma unroll
            for (int nb = 0; nb < 4; nb++)
                #pragma unroll
                for (int q = 0; q < 4; q++) acc[mi][nb][q] = 0.f;

        auto load_stage = [&](int s, int kc) {
            char* st = smem + s * STAGE_BYTES;
            const int k0 = kc * BKC;
            #pragma unroll
            for (int p = 0; p < 8; p++) {          // A: 256 rows x 8 segs
                const int c = tid + p * 256;
                const int r = c >> 3, sg = c & 7;
                const uint32_t so = (uint32_t)(r * (SPAD * 2) + sg * 16);
                const size_t g = (size_t)(row0 + r) * Kp + k0 + sg * 8;
                cp_async16(smem_u32(st + so), A + g);
            }
            #pragma unroll
            for (int p = 0; p < 2; p++) {          // B: 64 rows x 8 segs
                const int c = tid + p * 256;
                const int r = c >> 3, sg = c & 7;
                const uint32_t so = (uint32_t)(r * (SPAD * 2) + sg * 16);
                const size_t g = (size_t)(col0 + r) * Kp + k0 + sg * 8;
                cp_async16(smem_u32(st + A_BYTES + so), B + g);
            }
            asm volatile("cp.async.commit_group;\n" ::: "memory");
        };

        load_stage(0, 0);
        load_stage(1, 1);

        for (int i = 0; i < nchunk; i++) {
            if (i + 1 < nchunk) asm volatile("cp.async.wait_group 1;\n" ::: "memory");
            else                asm volatile("cp.async.wait_group 0;\n" ::: "memory");
            __syncthreads();

            const char* st = smem + (i & 1) * STAGE_BYTES;
            const uint32_t sA = smem_u32(st);
            const uint32_t sB = sA + A_BYTES;

            #pragma unroll
            for (int ks = 0; ks < BKC; ks += 16) {
                uint32_t ar[4][4], br[2][4];
                #pragma unroll
                for (int mi = 0; mi < 4; mi++) {
                    const uint32_t off =
                        (uint32_t)(((wm + mi * 16 + la_row) * SPAD + ks + la_col) * 2);
                    ldsm4(sA + off, ar[mi][0], ar[mi][1], ar[mi][2], ar[mi][3]);
                }
                #pragma unroll
                for (int np = 0; np < 2; np++) {
                    const uint32_t off =
                        (uint32_t)(((wn + np * 16 + lb_row) * SPAD + ks + lb_col) * 2);
                    ldsm4(sB + off, br[np][0], br[np][1], br[np][2], br[np][3]);
                }
                #pragma unroll
                for (int mi = 0; mi < 4; mi++) {
                    #pragma unroll
                    for (int nb = 0; nb < 4; nb++) {
                        mma_fp16(acc[mi][nb], ar[mi],
                                 br[nb >> 1][(nb & 1) * 2],
                                 br[nb >> 1][(nb & 1) * 2 + 1]);
                    }
                }
            }
            __syncthreads();
            if (i + 2 < nchunk) load_stage(i & 1, i + 2);
        }

        // -------- epilogue (register-only; no smem hazard with next tile) ----
        #pragma unroll
        for (int mi = 0; mi < 4; mi++) {
            #pragma unroll
            for (int nb = 0; nb < 4; nb++) {
                const int rg = row0 + wm + mi * 16 + (lane >> 2);
                const int cg = col0 + wn + nb * 8 + (lane & 3) * 2;
                float b0 = 0.f, b1 = 0.f;
                if (ACT == 2) {
                    if (cg < DOUT)     b0 = bias[cg];
                    if (cg + 1 < DOUT) b1 = bias[cg + 1];
                } else {
                    b0 = bias[cg];
                    b1 = bias[cg + 1];
                }
                const float* a = acc[mi][nb];
                #pragma unroll
                for (int h = 0; h < 2; h++) {
                    const int r = rg + h * 8;
                    float v0 = a[h * 2 + 0] + b0;
                    float v1 = a[h * 2 + 1] + b1;
                    if (ACT == 1) {
                        v0 = fmaxf(v0, 0.f);
                        v1 = fmaxf(v1, 0.f);
                        *(__half2*)(Ch + (size_t)r * ldc + cg) = __floats2half2_rn(v0, v1);
                    } else {
                        if (cg + 2 <= DOUT) {
                            float2 o;
                            o.x = 1.f / (1.f + __expf(-v0));
                            o.y = 1.f / (1.f + __expf(-v1));
                            *(float2*)(Cf + (size_t)r * DOUT + cg) = o;
                        }
                    }
                }
            }
        }
    }
}

// ---------------------------------------------------------------------------
extern "C" void kernel_launch(void* const* d_in, const int* in_sizes, int n_in,
                              void* d_out, int out_size) {
    const int*   x   = (const int*)  d_in[0];
    const float* emb = (const float*)d_in[1];
    const float* W1  = (const float*)d_in[2];
    const float* b1  = (const float*)d_in[3];
    const float* W2  = (const float*)d_in[4];
    const float* b2  = (const float*)d_in[5];
    const float* W3  = (const float*)d_in[6];
    const float* b3  = (const float*)d_in[7];
    float* out = (float*)d_out;

    f16 *h0, *h1, *h2, *w1, *w2, *w3;
    cudaGetSymbolAddress((void**)&h0, g_h0);
    cudaGetSymbolAddress((void**)&h1, g_h1);
    cudaGetSymbolAddress((void**)&h2, g_h2);
    cudaGetSymbolAddress((void**)&w1, g_W1);
    cudaGetSymbolAddress((void**)&w2, g_W2);
    cudaGetSymbolAddress((void**)&w3, g_W3);

    cudaFuncSetAttribute((const void*)prep_kernel,
                         cudaFuncAttributeMaxDynamicSharedMemorySize, PREP_SMEM);
    cudaFuncSetAttribute((const void*)mma_gemm_kernel<1>,
                         cudaFuncAttributeMaxDynamicSharedMemorySize, SMEM_TOTAL);
    cudaFuncSetAttribute((const void*)mma_gemm_kernel<2>,
                         cudaFuncAttributeMaxDynamicSharedMemorySize, SMEM_TOTAL);

    prep_kernel<<<PREP_BLKS, 256, PREP_SMEM>>>(x, emb, W1, W2, W3, w1, w2, w3, h0);

    {   // layer 1: ntiles = (8192/256) * (1024/64) = 32*16 = 512
        const int ntiles = (BATCH / BM) * (DH1 / BN);
        const int grid = ntiles < GEMM_GRID ? ntiles : GEMM_GRID;
        mma_gemm_kernel<1><<<grid, 256, SMEM_TOTAL>>>(
            h0, w1, b1, h1, nullptr, K1P, DH1, K1P / BKC, ntiles, DH1 / BN);
    }
    {   // layer 2: ntiles = 32 * 8 = 256
        const int ntiles = (BATCH / BM) * (DH2 / BN);
        const int grid = ntiles < GEMM_GRID ? ntiles : GEMM_GRID;
        mma_gemm_kernel<1><<<grid, 256, SMEM_TOTAL>>>(
            h1, w2, b2, h2, nullptr, DH1, DH2, DH1 / BKC, ntiles, DH2 / BN);
    }
    {   // layer 3: ntiles = 32 * 16 = 512
        const int ntiles = (BATCH / BM) * (N3P / BN);
        const int grid = ntiles < GEMM_GRID ? ntiles : GEMM_GRID;
        mma_gemm_kernel<2><<<grid, 256, SMEM_TOTAL>>>(
            h2, w3, b3, nullptr, out, DH2, 0, DH2 / BKC, ntiles, N3P / BN);
    }
}

// round 12
// speedup vs baseline: 1.0022x; 1.0022x over previous
#include <cuda_runtime.h>
#include <cuda_fp16.h>
#include <cstdint>

#define BATCH 8192
#define NFEAT 32
#define EDIM  64
#define VOCAB 1000
#define NPAIR 496
#define DIN   2544
#define K1P   2560
#define DH1   1024
#define DH2   512
#define DOUT  1000
#define N3P   1024

typedef __half f16;

// ---------------- scratch (device globals; no runtime allocation) ----------
__device__ f16 g_h0[(size_t)BATCH * K1P];
__device__ f16 g_h1[(size_t)BATCH * DH1];
__device__ f16 g_h2[(size_t)BATCH * DH2];
__device__ f16 g_W1[(size_t)DH1 * K1P];
__device__ f16 g_W2[(size_t)DH2 * DH1];
__device__ f16 g_W3[(size_t)N3P * DH2];

// ---------------- helpers ---------------------------------------------------
__device__ __forceinline__ uint32_t smem_u32(const void* p) {
    return (uint32_t)__cvta_generic_to_shared(p);
}
__device__ __forceinline__ void cp_async16(uint32_t dst, const void* src) {
    asm volatile("cp.async.cg.shared.global [%0], [%1], 16;\n" :: "r"(dst), "l"(src));
}
__device__ __forceinline__ void ldsm4(uint32_t addr, uint32_t& r0, uint32_t& r1,
                                      uint32_t& r2, uint32_t& r3) {
    asm volatile("ldmatrix.sync.aligned.m8n8.x4.shared.b16 {%0,%1,%2,%3}, [%4];\n"
                 : "=r"(r0), "=r"(r1), "=r"(r2), "=r"(r3) : "r"(addr));
}
__device__ __forceinline__ void mma_fp16(float c[4], const uint32_t a[4],
                                         uint32_t b0, uint32_t b1) {
    asm volatile("mma.sync.aligned.m16n8k16.row.col.f32.f16.f16.f32 "
                 "{%0,%1,%2,%3},{%4,%5,%6,%7},{%8,%9},{%0,%1,%2,%3};\n"
                 : "+f"(c[0]), "+f"(c[1]), "+f"(c[2]), "+f"(c[3])
                 : "r"(a[0]), "r"(a[1]), "r"(a[2]), "r"(a[3]), "r"(b0), "r"(b1));
}

// ---------------------------------------------------------------------------
// Fused prep kernel: weight converts + feature build (unchanged from R10)
// ---------------------------------------------------------------------------
#define CONV1_BLKS 2560
#define CONV2_BLKS 512
#define CONV3_BLKS 512
#define CONV_BLKS  (CONV1_BLKS + CONV2_BLKS + CONV3_BLKS)   // 3584
#define FEAT_BLKS  (BATCH / 8)                               // 1024
#define PREP_BLKS  (CONV_BLKS + FEAT_BLKS)                   // 4608

#define FB_E_STRIDE 72
#define FB_WARP_BYTES (32 * FB_E_STRIDE * 2 + 32 * 36 * 2)   // 6912
#define FB_PAIRS_BYTES 2048
#define PREP_SMEM (FB_PAIRS_BYTES + 8 * FB_WARP_BYTES)       // 57344

__device__ __forceinline__ void convert_body(char* sm,
                                             const float* __restrict__ W,
                                             f16* __restrict__ dst,
                                             int K, int N, int Kpad, int Npad,
                                             int cid, int nbx) {
    float (*t)[33] = (float(*)[33])sm;
    const int tx = threadIdx.x & 31;
    const int ty = threadIdx.x >> 5;
    const int n0 = (cid % nbx) * 32;
    const int k0 = (cid / nbx) * 32;
    for (int r = ty; r < 32; r += 8) {
        int k = k0 + r, n = n0 + tx;
        t[r][tx] = (k < K && n < N) ? W[(size_t)k * N + n] : 0.f;
    }
    __syncthreads();
    for (int r = ty; r < 32; r += 8) {
        int n = n0 + r, k = k0 + tx;
        if (n < Npad && k < Kpad)
            dst[(size_t)n * Kpad + k] = __float2half_rn(t[tx][r]);
    }
}

__global__ __launch_bounds__(256)
void prep_kernel(const int* __restrict__ x,
                 const float* __restrict__ emb,
                 const float* __restrict__ W1,
                 const float* __restrict__ W2,
                 const float* __restrict__ W3,
                 f16* __restrict__ w1, f16* __restrict__ w2, f16* __restrict__ w3,
                 f16* __restrict__ h0) {
    extern __shared__ __align__(16) char sm[];
    const int bid = blockIdx.x;

    if (bid < CONV1_BLKS) {
        convert_body(sm, W1, w1, DIN, DH1, K1P, DH1, bid, 32);
        return;
    }
    if (bid < CONV1_BLKS + CONV2_BLKS) {
        convert_body(sm, W2, w2, DH1, DH2, DH1, DH2, bid - CONV1_BLKS, 16);
        return;
    }
    if (bid < CONV_BLKS) {
        convert_body(sm, W3, w3, DH2, DOUT, DH2, N3P, bid - CONV1_BLKS - CONV2_BLKS, 32);
        return;
    }

    // ---------------- features ----------------
    const int fb   = bid - CONV_BLKS;
    const int tid  = threadIdx.x;
    const int wid  = tid >> 5;
    const int lane = tid & 31;
    const int b    = fb * 8 + wid;

    int* pairs_s = (int*)sm;
    f16* e_s    = (f16*)(sm + FB_PAIRS_BYTES + wid * FB_WARP_BYTES);
    f16* gram_s = e_s + 32 * FB_E_STRIDE;

    for (int p = tid; p < NPAIR; p += 256) {
        int i = 0, s = 0;
        while (p >= s + (NFEAT - 1 - i)) { s += NFEAT - 1 - i; i++; }
        pairs_s[p] = (i << 8) | (i + 1 + (p - s));
    }
    __syncthreads();

    const size_t base = (size_t)b * K1P;

    {
        const int f = lane;
        const int myidx = x[b * NFEAT + f];
        const float* src = emb + ((size_t)f * VOCAB + myidx) * EDIM;
        uint4 ob[8];
        #pragma unroll
        for (int q = 0; q < 8; q++) {
            const float4 v0 = *(const float4*)(src + q * 8);
            const float4 v1 = *(const float4*)(src + q * 8 + 4);
            __half2 p0 = __floats2half2_rn(v0.x, v0.y);
            __half2 p1 = __floats2half2_rn(v0.z, v0.w);
            __half2 p2 = __floats2half2_rn(v1.x, v1.y);
            __half2 p3 = __floats2half2_rn(v1.z, v1.w);
            ob[q] = make_uint4(*(uint32_t*)&p0, *(uint32_t*)&p1,
                               *(uint32_t*)&p2, *(uint32_t*)&p3);
            *(uint4*)(e_s + f * FB_E_STRIDE + q * 8) = ob[q];
        }
        #pragma unroll
        for (int q = 0; q < 8; q++)
            *(uint4*)(h0 + base + f * EDIM + q * 8) = ob[q];
    }
    __syncwarp();

    {
        const int la_row = lane & 15;
        const int la_col = (lane >> 4) << 3;
        const int lb_row = (lane & 7) + ((lane >> 4) << 3);
        const int lb_col = ((lane >> 3) & 1) << 3;

        float acc[2][4][4];
        #pragma unroll
        for (int mi = 0; mi < 2; mi++)
            #pragma unroll
            for (int nb = 0; nb < 4; nb++)
                #pragma unroll
                for (int q = 0; q < 4; q++) acc[mi][nb][q] = 0.f;

        #pragma unroll
        for (int ks = 0; ks < EDIM; ks += 16) {
            uint32_t ar[2][4], br[2][4];
            #pragma unroll
            for (int mi = 0; mi < 2; mi++) {
                const uint32_t off = (uint32_t)(((mi * 16 + la_row) * FB_E_STRIDE
                                                 + ks + la_col) * 2);
                ldsm4(smem_u32(e_s) + off, ar[mi][0], ar[mi][1], ar[mi][2], ar[mi][3]);
            }
            #pragma unroll
            for (int np = 0; np < 2; np++) {
                const uint32_t off = (uint32_t)(((np * 16 + lb_row) * FB_E_STRIDE
                                                 + ks + lb_col) * 2);
                ldsm4(smem_u32(e_s) + off, br[np][0], br[np][1], br[np][2], br[np][3]);
            }
            #pragma unroll
            for (int mi = 0; mi < 2; mi++)
                #pragma unroll
                for (int nb = 0; nb < 4; nb++)
                    mma_fp16(acc[mi][nb], ar[mi],
                             br[nb >> 1][(nb & 1) * 2],
                             br[nb >> 1][(nb & 1) * 2 + 1]);
        }

        #pragma unroll
        for (int mi = 0; mi < 2; mi++) {
            #pragma unroll
            for (int nb = 0; nb < 4; nb++) {
                const int r0 = mi * 16 + (lane >> 2);
                const int c0 = nb * 8 + (lane & 3) * 2;
                *(__half2*)(gram_s + r0 * 36 + c0) =
                    __floats2half2_rn(acc[mi][nb][0], acc[mi][nb][1]);
                *(__half2*)(gram_s + (r0 + 8) * 36 + c0) =
                    __floats2half2_rn(acc[mi][nb][2], acc[mi][nb][3]);
            }
        }
    }
    __syncwarp();

    for (int p = lane; p < NPAIR; p += 32) {
        const int pr = pairs_s[p];
        h0[base + NFEAT * EDIM + p] = gram_s[(pr >> 8) * 36 + (pr & 255)];
    }
    if (lane < K1P - DIN) h0[base + DIN + lane] = __float2half(0.f);
}

// ---------------------------------------------------------------------------
// Persistent fp16 tensor-core GEMM: C[M,N] = act( A @ B^T + bias )
// BM=256, BN=64, BK=64; 256 threads, warps 4(m) x 2(n), warp tile 64x32.
// 2-stage cp.async ring; 2 CTAs/SM; CTAs loop over tiles (col-fastest).
// ---------------------------------------------------------------------------
#define BM 256
#define BN 64
#define BKC 64
#define SPAD 72                           // halfs per row = 144B (16B-aligned)
#define A_BYTES (BM * SPAD * 2)           // 36864
#define B_BYTES (BN * SPAD * 2)           // 9216
#define STAGE_BYTES (A_BYTES + B_BYTES)   // 46080
#define SMEM_TOTAL (2 * STAGE_BYTES)      // 92160
#define GEMM_GRID 296                     // 2 * 148 SMs

template<int ACT>
__global__ __launch_bounds__(256, 2)
void mma_gemm_kernel(const f16* __restrict__ A, const f16* __restrict__ B,
                     const float* __restrict__ bias,
                     f16* __restrict__ Ch, float* __restrict__ Cf,
                     int Kp, int ldc, int nchunk, int ntiles, int ncolt) {
    extern __shared__ __align__(16) char smem[];

    const int tid  = threadIdx.x;
    const int lane = tid & 31;
    const int wid  = tid >> 5;
    const int wm   = (wid >> 1) * 64;
    const int wn   = (wid & 1) * 32;

    const int la_row = lane & 15;
    const int la_col = (lane >> 4) << 3;
    const int lb_row = (lane & 7) + ((lane >> 4) << 3);
    const int lb_col = ((lane >> 3) & 1) << 3;

    for (int t = blockIdx.x; t < ntiles; t += gridDim.x) {
        const int row0 = (t / ncolt) * BM;
        const int col0 = (t % ncolt) * BN;

        float acc[4][4][4];
        #pragma unroll
        for (int mi = 0; mi < 4; mi++)
            #pragma unroll
            for (int nb = 0; nb < 4; nb++)
                #pragma unroll
                for (int q = 0; q < 4; q++) acc[mi][nb][q] = 0.f;

        auto load_stage = [&](int s, int kc) {
            char* st = smem + s * STAGE_BYTES;
            const int k0 = kc * BKC;
            #pragma unroll
            for (int p = 0; p < 8; p++) {          // A: 256 rows x 8 segs
                const int c = tid + p * 256;
                const int r = c >> 3, sg = c & 7;
                const uint32_t so = (uint32_t)(r * (SPAD * 2) + sg * 16);
                const size_t g = (size_t)(row0 + r) * Kp + k0 + sg * 8;
                cp_async16(smem_u32(st + so), A + g);
            }
            #pragma unroll
            for (int p = 0; p < 2; p++) {          // B: 64 rows x 8 segs
                const int c = tid + p * 256;
                const int r = c >> 3, sg = c & 7;
                const uint32_t so = (uint32_t)(r * (SPAD * 2) + sg * 16);
                const size_t g = (size_t)(col0 + r) * Kp + k0 + sg * 8;
                cp_async16(smem_u32(st + A_BYTES + so), B + g);
            }
            asm volatile("cp.async.commit_group;\n" ::: "memory");
        };

        load_stage(0, 0);
        load_stage(1, 1);

        for (int i = 0; i < nchunk; i++) {
            if (i + 1 < nchunk) asm volatile("cp.async.wait_group 1;\n" ::: "memory");
            else                asm volatile("cp.async.wait_group 0;\n" ::: "memory");
            __syncthreads();

            const char* st = smem + (i & 1) * STAGE_BYTES;
            const uint32_t sA = smem_u32(st);
            const uint32_t sB = sA + A_BYTES;

            #pragma unroll
            for (int ks = 0; ks < BKC; ks += 16) {
                uint32_t ar[4][4], br[2][4];
                #pragma unroll
                for (int mi = 0; mi < 4; mi++) {
                    const uint32_t off =
                        (uint32_t)(((wm + mi * 16 + la_row) * SPAD + ks + la_col) * 2);
                    ldsm4(sA + off, ar[mi][0], ar[mi][1], ar[mi][2], ar[mi][3]);
                }
                #pragma unroll
                for (int np = 0; np < 2; np++) {
                    const uint32_t off =
                        (uint32_t)(((wn + np * 16 + lb_row) * SPAD + ks + lb_col) * 2);
                    ldsm4(sB + off, br[np][0], br[np][1], br[np][2], br[np][3]);
                }
                #pragma unroll
                for (int mi = 0; mi < 4; mi++) {
                    #pragma unroll
                    for (int nb = 0; nb < 4; nb++) {
                        mma_fp16(acc[mi][nb], ar[mi],
                                 br[nb >> 1][(nb & 1) * 2],
                                 br[nb >> 1][(nb & 1) * 2 + 1]);
                    }
                }
            }
            __syncthreads();
            if (i + 2 < nchunk) load_stage(i & 1, i + 2);
        }

        // -------- epilogue (register-only; no smem hazard with next tile) ----
        #pragma unroll
        for (int mi = 0; mi < 4; mi++) {
            #pragma unroll
            for (int nb = 0; nb < 4; nb++) {
                const int rg = row0 + wm + mi * 16 + (lane >> 2);
                const int cg = col0 + wn + nb * 8 + (lane & 3) * 2;
                float b0 = 0.f, b1 = 0.f;
                if (ACT == 2) {
                    if (cg < DOUT)     b0 = bias[cg];
                    if (cg + 1 < DOUT) b1 = bias[cg + 1];
                } else {
                    b0 = bias[cg];
                    b1 = bias[cg + 1];
                }
                const float* a = acc[mi][nb];
                #pragma unroll
                for (int h = 0; h < 2; h++) {
                    const int r = rg + h * 8;
                    float v0 = a[h * 2 + 0] + b0;
                    float v1 = a[h * 2 + 1] + b1;
                    if (ACT == 1) {
                        v0 = fmaxf(v0, 0.f);
                        v1 = fmaxf(v1, 0.f);
                        *(__half2*)(Ch + (size_t)r * ldc + cg) = __floats2half2_rn(v0, v1);
                    } else {
                        if (cg + 2 <= DOUT) {
                            float2 o;
                            o.x = 1.f / (1.f + __expf(-v0));
                            o.y = 1.f / (1.f + __expf(-v1));
                            *(float2*)(Cf + (size_t)r * DOUT + cg) = o;
                        }
                    }
                }
            }
        }
    }
}

// ---------------------------------------------------------------------------
extern "C" void kernel_launch(void* const* d_in, const int* in_sizes, int n_in,
                              void* d_out, int out_size) {
    const int*   x   = (const int*)  d_in[0];
    const float* emb = (const float*)d_in[1];
    const float* W1  = (const float*)d_in[2];
    const float* b1  = (const float*)d_in[3];
    const float* W2  = (const float*)d_in[4];
    const float* b2  = (const float*)d_in[5];
    const float* W3  = (const float*)d_in[6];
    const float* b3  = (const float*)d_in[7];
    float* out = (float*)d_out;

    f16 *h0, *h1, *h2, *w1, *w2, *w3;
    cudaGetSymbolAddress((void**)&h0, g_h0);
    cudaGetSymbolAddress((void**)&h1, g_h1);
    cudaGetSymbolAddress((void**)&h2, g_h2);
    cudaGetSymbolAddress((void**)&w1, g_W1);
    cudaGetSymbolAddress((void**)&w2, g_W2);
    cudaGetSymbolAddress((void**)&w3, g_W3);

    cudaFuncSetAttribute((const void*)prep_kernel,
                         cudaFuncAttributeMaxDynamicSharedMemorySize, PREP_SMEM);
    cudaFuncSetAttribute((const void*)mma_gemm_kernel<1>,
                         cudaFuncAttributeMaxDynamicSharedMemorySize, SMEM_TOTAL);
    cudaFuncSetAttribute((const void*)mma_gemm_kernel<2>,
                         cudaFuncAttributeMaxDynamicSharedMemorySize, SMEM_TOTAL);

    prep_kernel<<<PREP_BLKS, 256, PREP_SMEM>>>(x, emb, W1, W2, W3, w1, w2, w3, h0);

    {   // layer 1: ntiles = (8192/256) * (1024/64) = 32*16 = 512
        const int ntiles = (BATCH / BM) * (DH1 / BN);
        const int grid = ntiles < GEMM_GRID ? ntiles : GEMM_GRID;
        mma_gemm_kernel<1><<<grid, 256, SMEM_TOTAL>>>(
            h0, w1, b1, h1, nullptr, K1P, DH1, K1P / BKC, ntiles, DH1 / BN);
    }
    {   // layer 2: ntiles = 32 * 8 = 256
        const int ntiles = (BATCH / BM) * (DH2 / BN);
        const int grid = ntiles < GEMM_GRID ? ntiles : GEMM_GRID;
        mma_gemm_kernel<1><<<grid, 256, SMEM_TOTAL>>>(
            h1, w2, b2, h2, nullptr, DH1, DH2, DH1 / BKC, ntiles, DH2 / BN);
    }
    {   // layer 3: ntiles = 32 * 16 = 512
        const int ntiles = (BATCH / BM) * (N3P / BN);
        const int grid = ntiles < GEMM_GRID ? ntiles : GEMM_GRID;
        mma_gemm_kernel<2><<<grid, 256, SMEM_TOTAL>>>(
            h2, w3, b3, nullptr, out, DH2, 0, DH2 / BKC, ntiles, N3P / BN);
    }
}